// round 1
// baseline (speedup 1.0000x reference)
#include <cuda_runtime.h>
#include <math.h>

// ---------------- problem constants ----------------
#define NNODE   20000
#define NPAD    20096          // padded to multiple of 64 for GEMM
#define EDGES   640000
#define BB      256            // batch
#define DG      256            // GNN dim
#define DH      512            // hidden
#define DI      2048           // inner
#define RNK     512
#define NCLS    3
#define NGENE   6640
#define LN_EPS  1e-5f

// ---------------- scratch (device globals; no allocation allowed) ----------------
__device__ float g_x   [NPAD * DG];
__device__ float g_hln [NPAD * DG];
__device__ float g_agg [NPAD * DG];   // pad rows never written -> stay zero
__device__ int   g_deg [NNODE];
__device__ int   g_off [NNODE + 1];
__device__ int   g_cur [NNODE];
__device__ int   g_bsrc[EDGES];
__device__ float g_bw  [EDGES];
__device__ float g_xg  [BB * DG];
__device__ float g_pert[BB * DG];
__device__ float g_h   [BB * DH];
__device__ float g_z   [BB * DH];
__device__ float g_t   [BB * DI];
__device__ float g_part[4 * BB * DH];
__device__ float g_proj[BB * NCLS * RNK];

// ---------------- small kernels ----------------
__global__ void zero_deg_kernel(int* deg) {
    int i = blockIdx.x * blockDim.x + threadIdx.x;
    if (i < NNODE) deg[i] = 0;
}

__global__ void hist_kernel(const int* __restrict__ edge_index, int* __restrict__ deg) {
    int i = blockIdx.x * blockDim.x + threadIdx.x;
    if (i < EDGES) atomicAdd(&deg[edge_index[EDGES + i]], 1);
}

__global__ void scan_kernel(const int* __restrict__ deg, int* __restrict__ off, int n) {
    __shared__ int sh[1024];
    __shared__ int base_s;
    int tid = threadIdx.x;
    if (tid == 0) { base_s = 0; off[0] = 0; }
    __syncthreads();
    for (int start = 0; start < n; start += 1024) {
        int v = (start + tid < n) ? deg[start + tid] : 0;
        sh[tid] = v;
        __syncthreads();
        for (int o = 1; o < 1024; o <<= 1) {
            int u = (tid >= o) ? sh[tid - o] : 0;
            __syncthreads();
            sh[tid] += u;
            __syncthreads();
        }
        if (start + tid < n) off[start + tid + 1] = base_s + sh[tid];
        int tot = sh[1023];
        __syncthreads();
        if (tid == 0) base_s += tot;
        __syncthreads();
    }
}

__global__ void copy_cursor_kernel(const int* __restrict__ off, int* __restrict__ cur) {
    int i = blockIdx.x * blockDim.x + threadIdx.x;
    if (i < NNODE) cur[i] = off[i];
}

__global__ void scatter_kernel(const int* __restrict__ edge_index, const float* __restrict__ ew,
                               int* __restrict__ cur, int* __restrict__ bsrc, float* __restrict__ bw) {
    int i = blockIdx.x * blockDim.x + threadIdx.x;
    if (i < EDGES) {
        int d = edge_index[EDGES + i];
        int p = atomicAdd(&cur[d], 1);
        bsrc[p] = edge_index[i];
        bw[p]   = ew[i];
    }
}

__global__ void copy_x_kernel(const float* __restrict__ src, float* __restrict__ dst) {
    int i = blockIdx.x * blockDim.x + threadIdx.x;
    if (i < NPAD * DG) dst[i] = (i < NNODE * DG) ? src[i] : 0.0f;
}

// LayerNorm: one warp per row. D in {256, 512}.
__global__ void ln_kernel(const float* __restrict__ x, const float* __restrict__ s,
                          const float* __restrict__ b, float* __restrict__ y,
                          int rows, int D) {
    int wid = threadIdx.x >> 5, lane = threadIdx.x & 31;
    int row = blockIdx.x * (blockDim.x >> 5) + wid;
    if (row >= rows) return;
    const float4* xr = (const float4*)(x + (size_t)row * D);
    int nf = D >> 7;              // float4's per lane
    float4 r[4];
    float sum = 0.f;
    for (int t = 0; t < nf; ++t) {
        r[t] = xr[lane + 32 * t];
        sum += r[t].x + r[t].y + r[t].z + r[t].w;
    }
    for (int o = 16; o > 0; o >>= 1) sum += __shfl_xor_sync(0xffffffffu, sum, o);
    float mu = sum / (float)D;
    float vs = 0.f;
    for (int t = 0; t < nf; ++t) {
        float dx = r[t].x - mu, dy = r[t].y - mu, dz = r[t].z - mu, dw = r[t].w - mu;
        vs += dx * dx + dy * dy + dz * dz + dw * dw;
    }
    for (int o = 16; o > 0; o >>= 1) vs += __shfl_xor_sync(0xffffffffu, vs, o);
    float w = rsqrtf(vs / (float)D + LN_EPS);
    float4* yr = (float4*)(y + (size_t)row * D);
    for (int t = 0; t < nf; ++t) {
        int col = (lane + 32 * t) * 4;
        float4 o4;
        o4.x = (r[t].x - mu) * w * s[col + 0] + b[col + 0];
        o4.y = (r[t].y - mu) * w * s[col + 1] + b[col + 1];
        o4.z = (r[t].z - mu) * w * s[col + 2] + b[col + 2];
        o4.w = (r[t].w - mu) * w * s[col + 3] + b[col + 3];
        yr[lane + 32 * t] = o4;
    }
}

// CSR weighted aggregation: one warp per node, row accumulated in registers.
__global__ void agg_kernel(const float* __restrict__ hln, float* __restrict__ agg,
                           const int* __restrict__ off, const int* __restrict__ bsrc,
                           const float* __restrict__ bw) {
    int wid = threadIdx.x >> 5, lane = threadIdx.x & 31;
    int node = blockIdx.x * (blockDim.x >> 5) + wid;
    if (node >= NNODE) return;
    int st = off[node], en = off[node + 1];
    float4 a0 = make_float4(0, 0, 0, 0), a1 = make_float4(0, 0, 0, 0);
    for (int j = st; j < en; ++j) {
        int s = bsrc[j];
        float w = bw[j];
        const float4* r = (const float4*)(hln + s * DG);
        float4 v0 = r[lane], v1 = r[lane + 32];
        a0.x = fmaf(w, v0.x, a0.x); a0.y = fmaf(w, v0.y, a0.y);
        a0.z = fmaf(w, v0.z, a0.z); a0.w = fmaf(w, v0.w, a0.w);
        a1.x = fmaf(w, v1.x, a1.x); a1.y = fmaf(w, v1.y, a1.y);
        a1.z = fmaf(w, v1.z, a1.z); a1.w = fmaf(w, v1.w, a1.w);
    }
    float4* o = (float4*)(agg + node * DG);
    o[lane] = a0;
    o[lane + 32] = a1;
}

__global__ void gather_kernel(const float* __restrict__ x, const int* __restrict__ idx,
                              float* __restrict__ out) {
    int bi = blockIdx.x, j = threadIdx.x;
    int id = idx[bi];
    int safe = id < 0 ? 0 : id;
    out[bi * DG + j] = x[(size_t)safe * DG + j];
}

__global__ void oovfix_kernel(const int* __restrict__ idx, const float* __restrict__ oov_emb,
                              float* __restrict__ pert) {
    int bi = blockIdx.x, j = threadIdx.x;
    if (idx[bi] < 0) pert[bi * DG + j] = oov_emb[j];
}

// h[i] += bias[i%N] + sum_z part[z][i]
__global__ void reduceK_kernel(float* __restrict__ h, const float* __restrict__ part,
                               const float* __restrict__ bias, int S, int total, int N) {
    int i = blockIdx.x * blockDim.x + threadIdx.x;
    if (i < total) {
        float v = bias[i % N];
        for (int z = 0; z < S; ++z) v += part[(size_t)z * total + i];
        h[i] += v;
    }
}

// ---------------- GEMM: 64x64 tile, BK=16, 64 threads, 8x8 microtile ----------------
enum { EPI_NONE = 0, EPI_BIAS = 1, EPI_RELU_RES = 2, EPI_GELU = 3 };

template <bool BT>   // BT=false: B row-major [K,N];  BT=true: B row-major [N,K] (C = A @ B^T)
__global__ void __launch_bounds__(64) gemm64_kernel(
    const float* __restrict__ A, const float* __restrict__ B,
    const float* __restrict__ bias, const float* __restrict__ res,
    float* __restrict__ C, int M, int N, int K, int kChunk, int epi)
{
    __shared__ float As[16][68];
    __shared__ float Bs[16][68];
    int t  = threadIdx.x;
    int m0 = blockIdx.y * 64;
    int n0 = blockIdx.x * 64;
    int ks = blockIdx.z * kChunk;
    int ke = ks + kChunk; if (ke > K) ke = K;

    float acc[8][8];
#pragma unroll
    for (int i = 0; i < 8; ++i)
#pragma unroll
        for (int j = 0; j < 8; ++j) acc[i][j] = 0.f;

    int tx8 = (t & 7) * 8;
    int ty8 = (t >> 3) * 8;

    for (int k0 = ks; k0 < ke; k0 += 16) {
        // A tile (transpose into As[k][m])
#pragma unroll
        for (int j = 0; j < 4; ++j) {
            int f = j * 64 + t;
            int row = f >> 2;
            int kc  = (f & 3) << 2;
            int gm  = m0 + row;
            float4 v = make_float4(0, 0, 0, 0);
            if (gm < M) v = *(const float4*)(A + (size_t)gm * K + k0 + kc);
            As[kc + 0][row] = v.x; As[kc + 1][row] = v.y;
            As[kc + 2][row] = v.z; As[kc + 3][row] = v.w;
        }
        // B tile
        if (!BT) {
#pragma unroll
            for (int j = 0; j < 4; ++j) {
                int f = j * 64 + t;
                int kr = f >> 4;
                int nc = (f & 15) << 2;
                int gn = n0 + nc;
                float4 v = make_float4(0, 0, 0, 0);
                if (gn < N) v = *(const float4*)(B + (size_t)(k0 + kr) * N + gn);
                *(float4*)&Bs[kr][nc] = v;
            }
        } else {
#pragma unroll
            for (int j = 0; j < 4; ++j) {
                int f = j * 64 + t;
                int row = f >> 2;
                int kc  = (f & 3) << 2;
                int gn  = n0 + row;
                float4 v = make_float4(0, 0, 0, 0);
                if (gn < N) v = *(const float4*)(B + (size_t)gn * K + k0 + kc);
                Bs[kc + 0][row] = v.x; Bs[kc + 1][row] = v.y;
                Bs[kc + 2][row] = v.z; Bs[kc + 3][row] = v.w;
            }
        }
        __syncthreads();
#pragma unroll
        for (int kk = 0; kk < 16; ++kk) {
            float4 A0 = *(const float4*)&As[kk][ty8];
            float4 A1 = *(const float4*)&As[kk][ty8 + 4];
            float4 B0 = *(const float4*)&Bs[kk][tx8];
            float4 B1 = *(const float4*)&Bs[kk][tx8 + 4];
            float av[8] = {A0.x, A0.y, A0.z, A0.w, A1.x, A1.y, A1.z, A1.w};
            float bv[8] = {B0.x, B0.y, B0.z, B0.w, B1.x, B1.y, B1.z, B1.w};
#pragma unroll
            for (int i = 0; i < 8; ++i)
#pragma unroll
                for (int j = 0; j < 8; ++j)
                    acc[i][j] = fmaf(av[i], bv[j], acc[i][j]);
        }
        __syncthreads();
    }

    float* Cz = C + (size_t)blockIdx.z * M * N;
#pragma unroll
    for (int i = 0; i < 8; ++i) {
        int gm = m0 + ty8 + i;
        if (gm >= M) continue;
#pragma unroll
        for (int j = 0; j < 8; ++j) {
            int gn = n0 + tx8 + j;
            if (gn >= N) continue;
            float v = acc[i][j];
            if (epi != EPI_NONE && bias) v += bias[gn];
            if (epi == EPI_RELU_RES)      v = fmaxf(v, 0.f) + res[(size_t)gm * N + gn];
            else if (epi == EPI_GELU)     v = 0.5f * v * (1.f + erff(v * 0.70710678118654752f));
            Cz[(size_t)gm * N + gn] = v;
        }
    }
}

// ---------------- launch ----------------
extern "C" void kernel_launch(void* const* d_in, const int* in_sizes, int n_in,
                              void* d_out, int out_size) {
    const int*   node_indices = (const int*)d_in[0];
    const int*   edge_index   = (const int*)d_in[1];
    const float* edge_weight  = (const float*)d_in[2];
    const float* partial_emb  = (const float*)d_in[3];
    const float* oov_emb      = (const float*)d_in[4];
    const float* gnn_ln_s     = (const float*)d_in[5];
    const float* gnn_ln_b     = (const float*)d_in[6];
    const float* gnn_w        = (const float*)d_in[7];
    const float* gnn_b        = (const float*)d_in[8];
    const float* post_w       = (const float*)d_in[9];
    const float* post_b       = (const float*)d_in[10];
    const float* pin_w        = (const float*)d_in[11];
    const float* pin_b        = (const float*)d_in[12];
    const float* blk_ln_s     = (const float*)d_in[13];
    const float* blk_ln_b     = (const float*)d_in[14];
    const float* blk_w1       = (const float*)d_in[15];
    const float* blk_b1       = (const float*)d_in[16];
    const float* blk_w2       = (const float*)d_in[17];
    const float* blk_b2       = (const float*)d_in[18];
    const float* pout_w       = (const float*)d_in[19];
    const float* pout_b       = (const float*)d_in[20];
    const float* gene         = (const float*)d_in[21];
    float*       out          = (float*)d_out;

    static float *p_x = nullptr, *p_hln, *p_agg, *p_bw, *p_xg, *p_pert, *p_h, *p_z, *p_t, *p_part, *p_proj;
    static int   *p_deg, *p_off, *p_cur, *p_bsrc;
    if (!p_x) {
        cudaGetSymbolAddress((void**)&p_x,    g_x);
        cudaGetSymbolAddress((void**)&p_hln,  g_hln);
        cudaGetSymbolAddress((void**)&p_agg,  g_agg);
        cudaGetSymbolAddress((void**)&p_bw,   g_bw);
        cudaGetSymbolAddress((void**)&p_xg,   g_xg);
        cudaGetSymbolAddress((void**)&p_pert, g_pert);
        cudaGetSymbolAddress((void**)&p_h,    g_h);
        cudaGetSymbolAddress((void**)&p_z,    g_z);
        cudaGetSymbolAddress((void**)&p_t,    g_t);
        cudaGetSymbolAddress((void**)&p_part, g_part);
        cudaGetSymbolAddress((void**)&p_proj, g_proj);
        cudaGetSymbolAddress((void**)&p_deg,  g_deg);
        cudaGetSymbolAddress((void**)&p_off,  g_off);
        cudaGetSymbolAddress((void**)&p_cur,  g_cur);
        cudaGetSymbolAddress((void**)&p_bsrc, g_bsrc);
    }

    // ---- CSR binning of edges by dst (used by all 3 GNN layers) ----
    zero_deg_kernel<<<(NNODE + 255) / 256, 256>>>(p_deg);
    hist_kernel<<<(EDGES + 255) / 256, 256>>>(edge_index, p_deg);
    scan_kernel<<<1, 1024>>>(p_deg, p_off, NNODE);
    copy_cursor_kernel<<<(NNODE + 255) / 256, 256>>>(p_off, p_cur);
    scatter_kernel<<<(EDGES + 255) / 256, 256>>>(edge_index, edge_weight, p_cur, p_bsrc, p_bw);

    // ---- x = partial_emb (pad rows zero) ----
    copy_x_kernel<<<(NPAD * DG + 255) / 256, 256>>>(partial_emb, p_x);

    // ---- 3 GNN layers ----
    for (int i = 0; i < 3; ++i) {
        ln_kernel<<<NPAD / 8, 256>>>(p_x, gnn_ln_s + i * DG, gnn_ln_b + i * DG, p_hln, NPAD, DG);
        agg_kernel<<<(NNODE + 7) / 8, 256>>>(p_hln, p_agg, p_off, p_bsrc, p_bw);
        // x = relu(agg @ W + b) + x   (in-place)
        gemm64_kernel<false><<<dim3(DG / 64, NPAD / 64, 1), 64>>>(
            p_agg, gnn_w + (size_t)i * DG * DG, gnn_b + i * DG, p_x, p_x,
            NPAD, DG, DG, DG, EPI_RELU_RES);
    }

    // ---- gather 256 rows, then post_mp on just those rows ----
    gather_kernel<<<BB, DG>>>(p_x, node_indices, p_xg);
    gemm64_kernel<false><<<dim3(DG / 64, BB / 64, 1), 64>>>(
        p_xg, post_w, post_b, nullptr, p_pert, BB, DG, DG, DG, EPI_BIAS);
    oovfix_kernel<<<BB, DG>>>(node_indices, oov_emb, p_pert);

    // ---- proj_in ----
    gemm64_kernel<false><<<dim3(DH / 64, BB / 64, 1), 64>>>(
        p_pert, pin_w, pin_b, nullptr, p_h, BB, DH, DG, DG, EPI_BIAS);

    // ---- 6 residual MLP blocks ----
    for (int i = 0; i < 6; ++i) {
        ln_kernel<<<BB / 8, 256>>>(p_h, blk_ln_s + i * DH, blk_ln_b + i * DH, p_z, BB, DH);
        gemm64_kernel<false><<<dim3(DI / 64, BB / 64, 1), 64>>>(
            p_z, blk_w1 + (size_t)i * DH * DI, blk_b1 + i * DI, nullptr, p_t,
            BB, DI, DH, DH, EPI_GELU);
        // split-K x4 into partials, then deterministic reduce: h += sum + b2
        gemm64_kernel<false><<<dim3(DH / 64, BB / 64, 4), 64>>>(
            p_t, blk_w2 + (size_t)i * DI * DH, nullptr, nullptr, p_part,
            BB, DH, DI, DI / 4, EPI_NONE);
        reduceK_kernel<<<(BB * DH + 255) / 256, 256>>>(p_h, p_part, blk_b2 + i * DH, 4, BB * DH, DH);
    }

    // ---- proj_out ----
    gemm64_kernel<false><<<dim3((NCLS * RNK) / 64, BB / 64, 1), 64>>>(
        p_h, pout_w, pout_b, nullptr, p_proj, BB, NCLS * RNK, DH, DH, EPI_BIAS);

    // ---- logits = proj[768,512] @ gene[6640,512]^T ----
    gemm64_kernel<true><<<dim3((NGENE + 63) / 64, (BB * NCLS) / 64, 1), 64>>>(
        p_proj, gene, nullptr, nullptr, out, BB * NCLS, NGENE, RNK, RNK, EPI_BIAS);
}

// round 2
// speedup vs baseline: 1.5615x; 1.5615x over previous
#include <cuda_runtime.h>
#include <math.h>

// ---------------- problem constants ----------------
#define NNODE   20000
#define NPAD    20096          // padded to multiple of 128 for GEMM
#define EDGES   640000
#define BB      256            // batch
#define DG      256            // GNN dim
#define DH      512            // hidden
#define DI      2048           // inner
#define RNK     512
#define NCLS    3
#define NGENE   6640
#define LN_EPS  1e-5f

// ---------------- scratch (device globals; no allocation allowed) ----------------
__device__ float g_x   [NPAD * DG];
__device__ float g_hln [NPAD * DG];
__device__ float g_agg [NPAD * DG];   // pad rows never written -> stay zero
__device__ int   g_deg [NNODE];
__device__ int   g_off [NNODE + 1];
__device__ int   g_cur [NNODE];
__device__ int   g_bsrc[EDGES];
__device__ float g_bw  [EDGES];
__device__ float g_xg  [BB * DG];
__device__ float g_pert[BB * DG];
__device__ float g_h   [BB * DH];
__device__ float g_z   [BB * DH];
__device__ float g_t   [BB * DI];
__device__ float g_part[4 * BB * DI];     // split-K partials (max: w1, 4 x 256 x 2048)
__device__ float g_proj[BB * NCLS * RNK];

// ---------------- packed f32x2 helpers ----------------
__device__ __forceinline__ void ffma2(unsigned long long &d, unsigned long long a, unsigned long long b) {
    asm("fma.rn.f32x2 %0, %1, %2, %0;" : "+l"(d) : "l"(a), "l"(b));
}
__device__ __forceinline__ unsigned long long pack2(float x, float y) {
    unsigned long long r;
    asm("mov.b64 %0, {%1, %2};" : "=l"(r) : "f"(x), "f"(y));
    return r;
}
__device__ __forceinline__ float lo2(unsigned long long v) {
    return __uint_as_float((unsigned)(v & 0xffffffffull));
}
__device__ __forceinline__ float hi2(unsigned long long v) {
    return __uint_as_float((unsigned)(v >> 32));
}

// ---------------- small kernels ----------------
__global__ void zero_deg_kernel(int* deg) {
    int i = blockIdx.x * blockDim.x + threadIdx.x;
    if (i < NNODE) deg[i] = 0;
}

__global__ void hist_kernel(const int* __restrict__ edge_index, int* __restrict__ deg) {
    int i = blockIdx.x * blockDim.x + threadIdx.x;
    if (i < EDGES) atomicAdd(&deg[edge_index[EDGES + i]], 1);
}

__global__ void scan_kernel(const int* __restrict__ deg, int* __restrict__ off, int n) {
    __shared__ int sh[1024];
    __shared__ int base_s;
    int tid = threadIdx.x;
    if (tid == 0) { base_s = 0; off[0] = 0; }
    __syncthreads();
    for (int start = 0; start < n; start += 1024) {
        int v = (start + tid < n) ? deg[start + tid] : 0;
        sh[tid] = v;
        __syncthreads();
        for (int o = 1; o < 1024; o <<= 1) {
            int u = (tid >= o) ? sh[tid - o] : 0;
            __syncthreads();
            sh[tid] += u;
            __syncthreads();
        }
        if (start + tid < n) off[start + tid + 1] = base_s + sh[tid];
        int tot = sh[1023];
        __syncthreads();
        if (tid == 0) base_s += tot;
        __syncthreads();
    }
}

__global__ void copy_cursor_kernel(const int* __restrict__ off, int* __restrict__ cur) {
    int i = blockIdx.x * blockDim.x + threadIdx.x;
    if (i < NNODE) cur[i] = off[i];
}

__global__ void scatter_kernel(const int* __restrict__ edge_index, const float* __restrict__ ew,
                               int* __restrict__ cur, int* __restrict__ bsrc, float* __restrict__ bw) {
    int i = blockIdx.x * blockDim.x + threadIdx.x;
    if (i < EDGES) {
        int d = edge_index[EDGES + i];
        int p = atomicAdd(&cur[d], 1);
        bsrc[p] = edge_index[i];
        bw[p]   = ew[i];
    }
}

__global__ void copy_x_kernel(const float* __restrict__ src, float* __restrict__ dst) {
    int i = blockIdx.x * blockDim.x + threadIdx.x;
    if (i < NPAD * DG) dst[i] = (i < NNODE * DG) ? src[i] : 0.0f;
}

// LayerNorm: one warp per row. D in {256, 512}.
__global__ void ln_kernel(const float* __restrict__ x, const float* __restrict__ s,
                          const float* __restrict__ b, float* __restrict__ y,
                          int rows, int D) {
    int wid = threadIdx.x >> 5, lane = threadIdx.x & 31;
    int row = blockIdx.x * (blockDim.x >> 5) + wid;
    if (row >= rows) return;
    const float4* xr = (const float4*)(x + (size_t)row * D);
    int nf = D >> 7;              // float4's per lane
    float4 r[4];
    float sum = 0.f;
    for (int t = 0; t < nf; ++t) {
        r[t] = xr[lane + 32 * t];
        sum += r[t].x + r[t].y + r[t].z + r[t].w;
    }
    for (int o = 16; o > 0; o >>= 1) sum += __shfl_xor_sync(0xffffffffu, sum, o);
    float mu = sum / (float)D;
    float vs = 0.f;
    for (int t = 0; t < nf; ++t) {
        float dx = r[t].x - mu, dy = r[t].y - mu, dz = r[t].z - mu, dw = r[t].w - mu;
        vs += dx * dx + dy * dy + dz * dz + dw * dw;
    }
    for (int o = 16; o > 0; o >>= 1) vs += __shfl_xor_sync(0xffffffffu, vs, o);
    float w = rsqrtf(vs / (float)D + LN_EPS);
    float4* yr = (float4*)(y + (size_t)row * D);
    for (int t = 0; t < nf; ++t) {
        int col = (lane + 32 * t) * 4;
        float4 o4;
        o4.x = (r[t].x - mu) * w * s[col + 0] + b[col + 0];
        o4.y = (r[t].y - mu) * w * s[col + 1] + b[col + 1];
        o4.z = (r[t].z - mu) * w * s[col + 2] + b[col + 2];
        o4.w = (r[t].w - mu) * w * s[col + 3] + b[col + 3];
        yr[lane + 32 * t] = o4;
    }
}

// CSR weighted aggregation: one warp per node, row accumulated in registers.
__global__ void agg_kernel(const float* __restrict__ hln, float* __restrict__ agg,
                           const int* __restrict__ off, const int* __restrict__ bsrc,
                           const float* __restrict__ bw) {
    int wid = threadIdx.x >> 5, lane = threadIdx.x & 31;
    int node = blockIdx.x * (blockDim.x >> 5) + wid;
    if (node >= NNODE) return;
    int st = off[node], en = off[node + 1];
    float4 a0 = make_float4(0, 0, 0, 0), a1 = make_float4(0, 0, 0, 0);
    for (int j = st; j < en; ++j) {
        int s = bsrc[j];
        float w = bw[j];
        const float4* r = (const float4*)(hln + s * DG);
        float4 v0 = r[lane], v1 = r[lane + 32];
        a0.x = fmaf(w, v0.x, a0.x); a0.y = fmaf(w, v0.y, a0.y);
        a0.z = fmaf(w, v0.z, a0.z); a0.w = fmaf(w, v0.w, a0.w);
        a1.x = fmaf(w, v1.x, a1.x); a1.y = fmaf(w, v1.y, a1.y);
        a1.z = fmaf(w, v1.z, a1.z); a1.w = fmaf(w, v1.w, a1.w);
    }
    float4* o = (float4*)(agg + node * DG);
    o[lane] = a0;
    o[lane + 32] = a1;
}

__global__ void gather_kernel(const float* __restrict__ x, const int* __restrict__ idx,
                              float* __restrict__ out) {
    int bi = blockIdx.x, j = threadIdx.x;
    int id = idx[bi];
    int safe = id < 0 ? 0 : id;
    out[bi * DG + j] = x[(size_t)safe * DG + j];
}

__global__ void oovfix_kernel(const int* __restrict__ idx, const float* __restrict__ oov_emb,
                              float* __restrict__ pert) {
    int bi = blockIdx.x, j = threadIdx.x;
    if (idx[bi] < 0) pert[bi * DG + j] = oov_emb[j];
}

// Split-K reduce with epilogue.
// mode 0: dst = bias + sum
// mode 1: dst += bias + sum
// mode 2: dst = gelu(bias + sum)
__global__ void reduce_kernel(float* __restrict__ dst, const float* __restrict__ part,
                              const float* __restrict__ bias, int S, int total, int N, int mode) {
    int i = blockIdx.x * blockDim.x + threadIdx.x;
    if (i >= total) return;
    float v = bias[i % N];
    for (int z = 0; z < S; ++z) v += part[(size_t)z * total + i];
    if (mode == 2) v = 0.5f * v * (1.f + erff(v * 0.70710678118654752f));
    if (mode == 1) dst[i] += v;
    else           dst[i] = v;
}

// ---------------- GEMM: 128x64 tile, BK=16, 128 threads, 8x8 microtile (f32x2) ----------------
enum { EPI_NONE = 0, EPI_BIAS = 1, EPI_RELU_RES = 2 };

template <bool BT>   // BT=false: B row-major [K,N];  BT=true: B row-major [N,K] (C = A @ B^T)
__global__ void __launch_bounds__(128) gemmx_kernel(
    const float* __restrict__ A, const float* __restrict__ B,
    const float* __restrict__ bias, const float* __restrict__ res,
    float* __restrict__ C, int M, int N, int K, int kChunk, int epi)
{
    __shared__ float As[16][132];   // [k][m], m-pairs 8B aligned
    __shared__ float Bs[16][68];    // [k][n]
    int t  = threadIdx.x;
    int m0 = blockIdx.y * 128;
    int n0 = blockIdx.x * 64;
    int ks = blockIdx.z * kChunk;
    int ke = ks + kChunk; if (ke > K) ke = K;

    int tx8 = (t & 7) * 8;     // n offset within tile
    int ty8 = (t >> 3) * 8;    // m offset within tile

    unsigned long long acc[4][8];
#pragma unroll
    for (int p = 0; p < 4; ++p)
#pragma unroll
        for (int j = 0; j < 8; ++j) acc[p][j] = 0ull;

    for (int k0 = ks; k0 < ke; k0 += 16) {
        // A tile: 128 rows x 16 k, transpose into As[k][m]
#pragma unroll
        for (int j = 0; j < 4; ++j) {
            int f = j * 128 + t;
            int row = f >> 2;          // 0..127
            int kc  = (f & 3) << 2;    // 0,4,8,12
            int gm  = m0 + row;
            float4 v = make_float4(0, 0, 0, 0);
            if (gm < M) v = *(const float4*)(A + (size_t)gm * K + k0 + kc);
            As[kc + 0][row] = v.x; As[kc + 1][row] = v.y;
            As[kc + 2][row] = v.z; As[kc + 3][row] = v.w;
        }
        // B tile: 16 k x 64 n
        if (!BT) {
#pragma unroll
            for (int j = 0; j < 2; ++j) {
                int f = j * 128 + t;
                int kr = f >> 4;           // 0..15
                int nc = (f & 15) << 2;    // 0..60
                int gn = n0 + nc;
                float4 v = make_float4(0, 0, 0, 0);
                if (gn < N) v = *(const float4*)(B + (size_t)(k0 + kr) * N + gn);
                *(float4*)&Bs[kr][nc] = v;
            }
        } else {
#pragma unroll
            for (int j = 0; j < 2; ++j) {
                int f = j * 128 + t;
                int row = f >> 2;          // 0..63 (n)
                int kc  = (f & 3) << 2;
                int gn  = n0 + row;
                float4 v = make_float4(0, 0, 0, 0);
                if (gn < N) v = *(const float4*)(B + (size_t)gn * K + k0 + kc);
                Bs[kc + 0][row] = v.x; Bs[kc + 1][row] = v.y;
                Bs[kc + 2][row] = v.z; Bs[kc + 3][row] = v.w;
            }
        }
        __syncthreads();
#pragma unroll
        for (int kk = 0; kk < 16; ++kk) {
            const float* Ar = &As[kk][ty8];
            unsigned long long a0 = *(const unsigned long long*)(Ar + 0);
            unsigned long long a1 = *(const unsigned long long*)(Ar + 2);
            unsigned long long a2 = *(const unsigned long long*)(Ar + 4);
            unsigned long long a3 = *(const unsigned long long*)(Ar + 6);
            float4 b0 = *(const float4*)&Bs[kk][tx8];
            float4 b1 = *(const float4*)&Bs[kk][tx8 + 4];
            unsigned long long bd[8];
            bd[0] = pack2(b0.x, b0.x); bd[1] = pack2(b0.y, b0.y);
            bd[2] = pack2(b0.z, b0.z); bd[3] = pack2(b0.w, b0.w);
            bd[4] = pack2(b1.x, b1.x); bd[5] = pack2(b1.y, b1.y);
            bd[6] = pack2(b1.z, b1.z); bd[7] = pack2(b1.w, b1.w);
#pragma unroll
            for (int j = 0; j < 8; ++j) {
                ffma2(acc[0][j], a0, bd[j]);
                ffma2(acc[1][j], a1, bd[j]);
                ffma2(acc[2][j], a2, bd[j]);
                ffma2(acc[3][j], a3, bd[j]);
            }
        }
        __syncthreads();
    }

    float* Cz = C + (size_t)blockIdx.z * M * N;
    bool nfull = (n0 + 64 <= N);
#pragma unroll
    for (int p = 0; p < 4; ++p) {
#pragma unroll
        for (int h = 0; h < 2; ++h) {
            int gm = m0 + ty8 + 2 * p + h;
            if (gm >= M) continue;
            float v[8];
#pragma unroll
            for (int j = 0; j < 8; ++j) v[j] = h ? hi2(acc[p][j]) : lo2(acc[p][j]);
            int gn0 = n0 + tx8;
            if (epi == EPI_RELU_RES) {
                const float4 r0 = *(const float4*)(res + (size_t)gm * N + gn0);
                const float4 r1 = *(const float4*)(res + (size_t)gm * N + gn0 + 4);
#pragma unroll
                for (int j = 0; j < 8; ++j) {
                    float bi = bias[gn0 + j];
                    float rr = (j < 4) ? ((const float*)&r0)[j] : ((const float*)&r1)[j - 4];
                    v[j] = fmaxf(v[j] + bi, 0.f) + rr;
                }
            } else if (epi == EPI_BIAS) {
#pragma unroll
                for (int j = 0; j < 8; ++j) v[j] += bias[gn0 + j];
            }
            if (nfull) {
                float4 o0 = make_float4(v[0], v[1], v[2], v[3]);
                float4 o1 = make_float4(v[4], v[5], v[6], v[7]);
                *(float4*)(Cz + (size_t)gm * N + gn0)     = o0;
                *(float4*)(Cz + (size_t)gm * N + gn0 + 4) = o1;
            } else {
#pragma unroll
                for (int j = 0; j < 8; ++j)
                    if (gn0 + j < N) Cz[(size_t)gm * N + gn0 + j] = v[j];
            }
        }
    }
}

// ---------------- launch ----------------
extern "C" void kernel_launch(void* const* d_in, const int* in_sizes, int n_in,
                              void* d_out, int out_size) {
    const int*   node_indices = (const int*)d_in[0];
    const int*   edge_index   = (const int*)d_in[1];
    const float* edge_weight  = (const float*)d_in[2];
    const float* partial_emb  = (const float*)d_in[3];
    const float* oov_emb      = (const float*)d_in[4];
    const float* gnn_ln_s     = (const float*)d_in[5];
    const float* gnn_ln_b     = (const float*)d_in[6];
    const float* gnn_w        = (const float*)d_in[7];
    const float* gnn_b        = (const float*)d_in[8];
    const float* post_w       = (const float*)d_in[9];
    const float* post_b       = (const float*)d_in[10];
    const float* pin_w        = (const float*)d_in[11];
    const float* pin_b        = (const float*)d_in[12];
    const float* blk_ln_s     = (const float*)d_in[13];
    const float* blk_ln_b     = (const float*)d_in[14];
    const float* blk_w1       = (const float*)d_in[15];
    const float* blk_b1       = (const float*)d_in[16];
    const float* blk_w2       = (const float*)d_in[17];
    const float* blk_b2       = (const float*)d_in[18];
    const float* pout_w       = (const float*)d_in[19];
    const float* pout_b       = (const float*)d_in[20];
    const float* gene         = (const float*)d_in[21];
    float*       out          = (float*)d_out;

    static float *p_x = nullptr, *p_hln, *p_agg, *p_bw, *p_xg, *p_pert, *p_h, *p_z, *p_t, *p_part, *p_proj;
    static int   *p_deg, *p_off, *p_cur, *p_bsrc;
    if (!p_x) {
        cudaGetSymbolAddress((void**)&p_x,    g_x);
        cudaGetSymbolAddress((void**)&p_hln,  g_hln);
        cudaGetSymbolAddress((void**)&p_agg,  g_agg);
        cudaGetSymbolAddress((void**)&p_bw,   g_bw);
        cudaGetSymbolAddress((void**)&p_xg,   g_xg);
        cudaGetSymbolAddress((void**)&p_pert, g_pert);
        cudaGetSymbolAddress((void**)&p_h,    g_h);
        cudaGetSymbolAddress((void**)&p_z,    g_z);
        cudaGetSymbolAddress((void**)&p_t,    g_t);
        cudaGetSymbolAddress((void**)&p_part, g_part);
        cudaGetSymbolAddress((void**)&p_proj, g_proj);
        cudaGetSymbolAddress((void**)&p_deg,  g_deg);
        cudaGetSymbolAddress((void**)&p_off,  g_off);
        cudaGetSymbolAddress((void**)&p_cur,  g_cur);
        cudaGetSymbolAddress((void**)&p_bsrc, g_bsrc);
    }

    // ---- CSR binning of edges by dst ----
    zero_deg_kernel<<<(NNODE + 255) / 256, 256>>>(p_deg);
    hist_kernel<<<(EDGES + 255) / 256, 256>>>(edge_index, p_deg);
    scan_kernel<<<1, 1024>>>(p_deg, p_off, NNODE);
    copy_cursor_kernel<<<(NNODE + 255) / 256, 256>>>(p_off, p_cur);
    scatter_kernel<<<(EDGES + 255) / 256, 256>>>(edge_index, edge_weight, p_cur, p_bsrc, p_bw);

    // ---- x = partial_emb (pad rows zero) ----
    copy_x_kernel<<<(NPAD * DG + 255) / 256, 256>>>(partial_emb, p_x);

    // ---- 3 GNN layers ----
    for (int i = 0; i < 3; ++i) {
        ln_kernel<<<NPAD / 8, 256>>>(p_x, gnn_ln_s + i * DG, gnn_ln_b + i * DG, p_hln, NPAD, DG);
        agg_kernel<<<(NNODE + 7) / 8, 256>>>(p_hln, p_agg, p_off, p_bsrc, p_bw);
        // x = relu(agg @ W + b) + x   (in-place)
        gemmx_kernel<false><<<dim3(DG / 64, NPAD / 128, 1), 128>>>(
            p_agg, gnn_w + (size_t)i * DG * DG, gnn_b + i * DG, p_x, p_x,
            NPAD, DG, DG, DG, EPI_RELU_RES);
    }

    // ---- gather 256 rows, then post_mp on just those rows ----
    gather_kernel<<<BB, DG>>>(p_x, node_indices, p_xg);
    gemmx_kernel<false><<<dim3(DG / 64, BB / 128, 1), 128>>>(
        p_xg, post_w, post_b, nullptr, p_pert, BB, DG, DG, DG, EPI_BIAS);
    oovfix_kernel<<<BB, DG>>>(node_indices, oov_emb, p_pert);

    // ---- proj_in ----
    gemmx_kernel<false><<<dim3(DH / 64, BB / 128, 1), 128>>>(
        p_pert, pin_w, pin_b, nullptr, p_h, BB, DH, DG, DG, EPI_BIAS);

    // ---- 6 residual MLP blocks ----
    for (int i = 0; i < 6; ++i) {
        ln_kernel<<<BB / 8, 256>>>(p_h, blk_ln_s + i * DH, blk_ln_b + i * DH, p_z, BB, DH);
        // t = gelu(z @ W1 + b1), split-K x4
        gemmx_kernel<false><<<dim3(DI / 64, BB / 128, 4), 128>>>(
            p_z, blk_w1 + (size_t)i * DH * DI, nullptr, nullptr, p_part,
            BB, DI, DH, DH / 4, EPI_NONE);
        reduce_kernel<<<(BB * DI + 255) / 256, 256>>>(p_t, p_part, blk_b1 + i * DI, 4, BB * DI, DI, 2);
        // h += t @ W2 + b2, split-K x8
        gemmx_kernel<false><<<dim3(DH / 64, BB / 128, 8), 128>>>(
            p_t, blk_w2 + (size_t)i * DI * DH, nullptr, nullptr, p_part,
            BB, DH, DI, DI / 8, EPI_NONE);
        reduce_kernel<<<(BB * DH + 255) / 256, 256>>>(p_h, p_part, blk_b2 + i * DH, 8, BB * DH, DH, 1);
    }

    // ---- proj_out (split-K x2) ----
    gemmx_kernel<false><<<dim3((NCLS * RNK) / 64, BB / 128, 2), 128>>>(
        p_h, pout_w, nullptr, nullptr, p_part, BB, NCLS * RNK, DH, DH / 2, EPI_NONE);
    reduce_kernel<<<(BB * NCLS * RNK + 255) / 256, 256>>>(p_proj, p_part, pout_b, 2, BB * NCLS * RNK, NCLS * RNK, 0);

    // ---- logits = proj[768,512] @ gene[6640,512]^T ----
    gemmx_kernel<true><<<dim3((NGENE + 63) / 64, (BB * NCLS) / 128, 1), 128>>>(
        p_proj, gene, nullptr, nullptr, out, BB * NCLS, NGENE, RNK, RNK, EPI_NONE);
}